// round 12
// baseline (speedup 1.0000x reference)
#include <cuda_runtime.h>
#include <cuda_bf16.h>
#include <cstdint>

// Problem constants
constexpr int cB = 8;
constexpr int cN = 1024;
constexpr int cC = 640;
constexpr int cH = 8;
constexpr int cD = 80;
constexpr int cR = 3;
constexpr int cInner = cH * cD;        // 640
constexpr int cM = cB * cN;            // 8192
constexpr float SCALE = 0.11180339887498949f;  // 80^-0.5

// Scratch
__device__ float g_q[cM * cInner];
__device__ float g_k[cM * cInner];
__device__ float g_v[cM * cInner];
__device__ float g_ao[cM * cInner];
__device__ float g_xr[cM * cC];            // pre-rounded x
__device__ float g_wq[cInner * cC];        // pre-rounded weights
__device__ float g_wk[cInner * cC];
__device__ float g_wv[cInner * cC];
__device__ float g_wo[cC * cInner];

// ---------------------------------------------------------------------------
// helpers
// ---------------------------------------------------------------------------
__device__ __forceinline__ uint32_t smem_u32(const void* p) {
    uint32_t a;
    asm("{ .reg .u64 t; cvta.to.shared.u64 t, %1; cvt.u32.u64 %0, t; }"
        : "=r"(a) : "l"(p));
    return a;
}
__device__ __forceinline__ uint32_t tf32r(float x) {
    uint32_t r;
    asm("cvt.rna.tf32.f32 %0, %1;" : "=r"(r) : "f"(x));
    return r;
}
__device__ __forceinline__ float tf32rf(float x) {
    return __uint_as_float(tf32r(x));
}
__device__ __forceinline__ void mma_tf32(float* c, const uint32_t* a,
                                         uint32_t b0, uint32_t b1) {
    asm volatile(
        "mma.sync.aligned.m16n8k8.row.col.f32.tf32.tf32.f32 "
        "{%0,%1,%2,%3}, {%4,%5,%6,%7}, {%8,%9}, {%0,%1,%2,%3};"
        : "+f"(c[0]), "+f"(c[1]), "+f"(c[2]), "+f"(c[3])
        : "r"(a[0]), "r"(a[1]), "r"(a[2]), "r"(a[3]), "r"(b0), "r"(b1));
}
__device__ __forceinline__ void cp_async16(uint32_t dst, const void* src) {
    asm volatile("cp.async.ca.shared.global [%0], [%1], 16;" :: "r"(dst), "l"(src));
}
__device__ __forceinline__ void cp_commit() {
    asm volatile("cp.async.commit_group;" ::: "memory");
}
template <int N>
__device__ __forceinline__ void cp_wait() {
    asm volatile("cp.async.wait_group %0;" :: "n"(N) : "memory");
}

// ---------------------------------------------------------------------------
// Pre-round kernels (remove all CVT from GEMM hot loops).
// ---------------------------------------------------------------------------
__global__ void pre_round_x(const float* __restrict__ s, float* __restrict__ d) {
    const int i = (blockIdx.x * 256 + threadIdx.x) * 4;
    float4 v = *(const float4*)(s + i);
    *(float4*)(d + i) = make_float4(tf32rf(v.x), tf32rf(v.y), tf32rf(v.z), tf32rf(v.w));
}
__global__ void pre_round_w(const float* __restrict__ s0, const float* __restrict__ s1,
                            const float* __restrict__ s2, const float* __restrict__ s3,
                            float* __restrict__ d0, float* __restrict__ d1,
                            float* __restrict__ d2, float* __restrict__ d3) {
    const int z = blockIdx.z;
    const float* s = (z == 0) ? s0 : (z == 1) ? s1 : (z == 2) ? s2 : s3;
    float* d = (z == 0) ? d0 : (z == 1) ? d1 : (z == 2) ? d2 : d3;
    const int i = (blockIdx.x * 256 + threadIdx.x) * 4;
    float4 v = *(const float4*)(s + i);
    *(float4*)(d + i) = make_float4(tf32rf(v.x), tf32rf(v.y), tf32rf(v.z), tf32rf(v.w));
}

// ---------------------------------------------------------------------------
// tf32 GEMM, cp.async double-buffered, pre-rounded inputs (raw LDS frags).
// gridDim.z fuses up to 3 (B, C) pairs.  doRound: epilogue tf32rf(val*pm).
// (unchanged — round-10 proven)
// ---------------------------------------------------------------------------
constexpr int GP2  = 36;
constexpr int GBUF = 128 * GP2;
constexpr int GEMM_SMEM = 4 * GBUF * 4;     // 73728 B

__global__ __launch_bounds__(256, 2) void gemm_tf32(
    const float* __restrict__ A,
    const float* __restrict__ B0, const float* __restrict__ B1,
    const float* __restrict__ B2,
    float* __restrict__ C0, float* __restrict__ C1, float* __restrict__ C2,
    const float* __restrict__ bias,
    int M, int Nc, int K, float pm, int doRound)
{
    extern __shared__ float gsm[];
    float* As = gsm;
    float* Bs = gsm + 2 * GBUF;

    const int z = blockIdx.z;
    const float* Bm = (z == 0) ? B0 : (z == 1) ? B1 : B2;
    float* C = (z == 0) ? C0 : (z == 1) ? C1 : C2;
    const float pmz = (z == 0) ? pm : 1.0f;

    const int tid  = threadIdx.x;
    const int wid  = tid >> 5;
    const int lane = tid & 31;
    const int gid  = lane >> 2;
    const int tig  = lane & 3;
    const int wm   = (wid & 1) * 64;
    const int wn   = (wid >> 1) * 32;

    const int srow = tid >> 1;
    const int skc  = (tid & 1) * 16;

    const float* Ap = A  + (size_t)(blockIdx.y * 128 + srow) * K + skc;
    const float* Bp = Bm + (size_t)(blockIdx.x * 128 + srow) * K + skc;
    const uint32_t sA = smem_u32(As) + (srow * GP2 + skc) * 4;
    const uint32_t sB = smem_u32(Bs) + (srow * GP2 + skc) * 4;
    const uint32_t bufB = GBUF * 4;

    float acc[4][4][4];
#pragma unroll
    for (int mi = 0; mi < 4; mi++)
#pragma unroll
        for (int nj = 0; nj < 4; nj++)
#pragma unroll
            for (int j = 0; j < 4; j++) acc[mi][nj][j] = 0.f;

    const int nk = K >> 5;

#pragma unroll
    for (int i = 0; i < 4; i++) {
        cp_async16(sA + i * 16, Ap + i * 4);
        cp_async16(sB + i * 16, Bp + i * 4);
    }
    cp_commit();

#pragma unroll 1
    for (int t = 0; t < nk; t++) {
        if (t + 1 < nk) {
            const uint32_t bo = (uint32_t)((t + 1) & 1) * bufB;
            const float* ap = Ap + (t + 1) * 32;
            const float* bp = Bp + (t + 1) * 32;
#pragma unroll
            for (int i = 0; i < 4; i++) {
                cp_async16(sA + bo + i * 16, ap + i * 4);
                cp_async16(sB + bo + i * 16, bp + i * 4);
            }
            cp_commit();
            cp_wait<1>();
        } else {
            cp_wait<0>();
        }
        __syncthreads();

        const float* Ab = As + (t & 1) * GBUF;
        const float* Bb = Bs + (t & 1) * GBUF;

#pragma unroll
        for (int ks = 0; ks < 4; ks++) {
            uint32_t af[4][4];
#pragma unroll
            for (int mi = 0; mi < 4; mi++) {
                const float* p0 = Ab + (wm + mi * 16 + gid) * GP2 + ks * 8 + tig;
                af[mi][0] = __float_as_uint(p0[0]);
                af[mi][1] = __float_as_uint(p0[8 * GP2]);
                af[mi][2] = __float_as_uint(p0[4]);
                af[mi][3] = __float_as_uint(p0[8 * GP2 + 4]);
            }
#pragma unroll
            for (int nj = 0; nj < 4; nj++) {
                const float* p = Bb + (wn + nj * 8 + gid) * GP2 + ks * 8 + tig;
                const uint32_t b0 = __float_as_uint(p[0]);
                const uint32_t b1 = __float_as_uint(p[4]);
#pragma unroll
                for (int mi = 0; mi < 4; mi++)
                    mma_tf32(acc[mi][nj], af[mi], b0, b1);
            }
        }
        __syncthreads();
    }

#pragma unroll
    for (int nj = 0; nj < 4; nj++) {
        const int col = blockIdx.x * 128 + wn + nj * 8 + tig * 2;
        const float ba0 = bias ? bias[col]     : 0.f;
        const float ba1 = bias ? bias[col + 1] : 0.f;
#pragma unroll
        for (int mi = 0; mi < 4; mi++) {
            const int row = blockIdx.y * 128 + wm + mi * 16 + gid;
            float* cp = C + (size_t)row * Nc + col;
            float v00 = acc[mi][nj][0] + ba0;
            float v01 = acc[mi][nj][1] + ba1;
            float v10 = acc[mi][nj][2] + ba0;
            float v11 = acc[mi][nj][3] + ba1;
            if (doRound) {
                v00 = tf32rf(v00 * pmz); v01 = tf32rf(v01 * pmz);
                v10 = tf32rf(v10 * pmz); v11 = tf32rf(v11 * pmz);
            }
            *(float2*)cp = make_float2(v00, v01);
            *(float2*)(cp + (size_t)8 * Nc) = make_float2(v10, v11);
        }
    }
}

// ---------------------------------------------------------------------------
// Flash attention, mma.sync tf32.  EXACT round-10 math and inner loops,
// re-partitioned for 2 CTAs/SM: 128-thread CTA (4 warps), 64 queries x
// 128 keys per tile.  Per-warp work per barrier unchanged (16q x 128k =
// 320 HMMA); co-resident CTAs overlap each other's staging/barriers.
// Budget: regs ~194 x 256 thr = 49.7K < 64K;  smem 111616 B x 2 <= 227 KB.
// Layouts: K interleaved Ks[key][(d&~7)+2(d&3)+((d>>2)&1)] pitch 88 (r10);
// V row-major pitch 88; no-max softmax with epilogue-only row reduction.
// ---------------------------------------------------------------------------
constexpr int QSP = 84;
constexpr int KSP = 88;                   // %32==24: LDS.64 frags conflict-free
constexpr int VSP = 88;
constexpr int SM_KS = 64 * QSP;           // word offsets (Q is 64 rows)
constexpr int SM_VS = SM_KS + 128 * KSP;
constexpr int ATTN_SMEM = (SM_VS + 128 * VSP) * 4;   // 111616 bytes

__global__ __launch_bounds__(128, 2) void attn_mma(const int* __restrict__ ctx)
{
    extern __shared__ float sm[];
    float* Qs = sm;
    float* Ks = sm + SM_KS;
    float* Vs = sm + SM_VS;

    const int tid  = threadIdx.x;
    const int wid  = tid >> 5;       // 0..3
    const int lane = tid & 31;
    const int gid  = lane >> 2;
    const int tig  = lane & 3;
    const int m0   = wid * 16;       // warp's first query row (0..48)

    const int qt = blockIdx.x, h = blockIdx.y, b = blockIdx.z;

    const int qrow = tid >> 1;           // 0..63  (Q staging row)
    const int qd0  = (tid & 1) * 40;     // 0/40
    const int kvrow = tid;               // 0..127 (KV staging row, full d)

    const int frame0 = ctx[b * cR + 0];
    const int frame1 = ctx[b * cR + 1];
    const int frame2 = ctx[b * cR + 2];

    // ---- stage Q (64 x 80; pre-scaled, pre-rounded: pure copy) ----
    {
        const float* qp = g_q + (size_t)(b * cN + qt * 64 + qrow) * cInner + h * cD + qd0;
        float* qs = Qs + qrow * QSP + qd0;
#pragma unroll
        for (int i = 0; i < 10; i++)
            *(float4*)(qs + i * 4) = *(const float4*)(qp + i * 4);
    }
    __syncthreads();

    // ---- Q A-fragments in registers (reused for all 24 KV tiles) ----
    uint32_t qa[10][4];
#pragma unroll
    for (int k = 0; k < 10; k++) {
        qa[k][0] = __float_as_uint(Qs[(m0 + gid) * QSP + k * 8 + tig]);
        qa[k][1] = __float_as_uint(Qs[(m0 + gid + 8) * QSP + k * 8 + tig]);
        qa[k][2] = __float_as_uint(Qs[(m0 + gid) * QSP + k * 8 + tig + 4]);
        qa[k][3] = __float_as_uint(Qs[(m0 + gid + 8) * QSP + k * 8 + tig + 4]);
    }

    float o[10][4];
#pragma unroll
    for (int n = 0; n < 10; n++)
#pragma unroll
        for (int j = 0; j < 4; j++) o[n][j] = 0.f;
    float llo = 0.f, lhi = 0.f;      // lane-partial row sums

    const int sh1 = (lane & 28) | (tig >> 1);
    const int sh2 = sh1 + 2;
    const bool odd = (tig & 1);

#pragma unroll 1
    for (int t = 0; t < 24; t++) {
        __syncthreads();   // prev tile's readers done before overwrite

        // ---- stage K (interleaved via register permute) and V (row copy) ----
        {
            const int frame = (t >> 3) == 0 ? frame0 : (t >> 3) == 1 ? frame1 : frame2;
            const int kb = (t * 128) & (cN - 1);
            const size_t gof = (size_t)(frame * cN + kb + kvrow) * cInner + h * cD;
            const float* kp = g_k + gof;
            const float* vp = g_v + gof;
            float* ks = Ks + kvrow * KSP;
            float* vs = Vs + kvrow * VSP;
#pragma unroll
            for (int g = 0; g < 10; g++) {
                const int base = g * 8;
                float4 ka = *(const float4*)(kp + base);
                float4 kc = *(const float4*)(kp + base + 4);
                *(float4*)(ks + base)     = make_float4(ka.x, kc.x, ka.y, kc.y);
                *(float4*)(ks + base + 4) = make_float4(ka.z, kc.z, ka.w, kc.w);
                *(float4*)(vs + base)     = *(const float4*)(vp + base);
                *(float4*)(vs + base + 4) = *(const float4*)(vp + base + 4);
            }
        }
        __syncthreads();

        // ---- S = Q K^T : 16 n-tiles x 10 k-steps, B-pairs via LDS.64 ----
        float s[16][4];
#pragma unroll
        for (int n = 0; n < 16; n++)
#pragma unroll
            for (int j = 0; j < 4; j++) s[n][j] = 0.f;

#pragma unroll
        for (int n = 0; n < 16; n++) {
            const float* krow = Ks + (n * 8 + gid) * KSP + 2 * tig;
#pragma unroll
            for (int k = 0; k < 10; k++) {
                float2 bb = *(const float2*)(krow + k * 8);
                mma_tf32(s[n], qa[k], __float_as_uint(bb.x), __float_as_uint(bb.y));
            }
        }

        // ---- softmax numerator (no max subtraction; logits bounded) ----
        float rs0 = 0.f, rs1 = 0.f;
#pragma unroll
        for (int n = 0; n < 16; n++) {
            s[n][0] = __expf(s[n][0]); rs0 += s[n][0];
            s[n][1] = __expf(s[n][1]); rs0 += s[n][1];
            s[n][2] = __expf(s[n][2]); rs1 += s[n][2];
            s[n][3] = __expf(s[n][3]); rs1 += s[n][3];
        }
        llo += rs0;
        lhi += rs1;

        // ---- O += P V : 16 k-tiles x 10 n-tiles ----
#pragma unroll
        for (int kt = 0; kt < 16; kt++) {
            float v00 = __shfl_sync(0xffffffffu, s[kt][0], sh1);
            float v01 = __shfl_sync(0xffffffffu, s[kt][1], sh1);
            float v02 = __shfl_sync(0xffffffffu, s[kt][0], sh2);
            float v03 = __shfl_sync(0xffffffffu, s[kt][1], sh2);
            float v10 = __shfl_sync(0xffffffffu, s[kt][2], sh1);
            float v11 = __shfl_sync(0xffffffffu, s[kt][3], sh1);
            float v12 = __shfl_sync(0xffffffffu, s[kt][2], sh2);
            float v13 = __shfl_sync(0xffffffffu, s[kt][3], sh2);
            uint32_t pa[4];
            pa[0] = tf32r(odd ? v01 : v00);
            pa[1] = tf32r(odd ? v11 : v10);
            pa[2] = tf32r(odd ? v03 : v02);
            pa[3] = tf32r(odd ? v13 : v12);

            const float* vrow0 = Vs + (kt * 8 + tig) * VSP + gid;
            const float* vrow1 = Vs + (kt * 8 + tig + 4) * VSP + gid;
#pragma unroll
            for (int n = 0; n < 10; n++) {
                uint32_t b0 = __float_as_uint(vrow0[n * 8]);
                uint32_t b1 = __float_as_uint(vrow1[n * 8]);
                mma_tf32(o[n], pa, b0, b1);
            }
        }
    }

    // ---- epilogue: reduce row sums once, normalize, pre-round ----
    llo += __shfl_xor_sync(0xffffffffu, llo, 1);
    llo += __shfl_xor_sync(0xffffffffu, llo, 2);
    lhi += __shfl_xor_sync(0xffffffffu, lhi, 1);
    lhi += __shfl_xor_sync(0xffffffffu, lhi, 2);
    const float inv0 = 1.f / llo;
    const float inv1 = 1.f / lhi;
    float* op0 = g_ao + (size_t)(b * cN + qt * 64 + m0 + gid) * cInner + h * cD;
    float* op1 = op0 + (size_t)8 * cInner;
#pragma unroll
    for (int n = 0; n < 10; n++) {
        *(float2*)(op0 + n * 8 + tig * 2) =
            make_float2(tf32rf(o[n][0] * inv0), tf32rf(o[n][1] * inv0));
        *(float2*)(op1 + n * 8 + tig * 2) =
            make_float2(tf32rf(o[n][2] * inv1), tf32rf(o[n][3] * inv1));
    }
}

// ---------------------------------------------------------------------------
extern "C" void kernel_launch(void* const* d_in, const int* in_sizes, int n_in,
                              void* d_out, int out_size)
{
    const float* x   = (const float*)d_in[0];
    const float* Wq  = (const float*)d_in[1];
    const float* Wk  = (const float*)d_in[2];
    const float* Wv  = (const float*)d_in[3];
    const float* Wo  = (const float*)d_in[4];
    const float* bo  = (const float*)d_in[5];
    const int*   ctx = (const int*)d_in[6];
    float* out = (float*)d_out;

    float* gq;  cudaGetSymbolAddress((void**)&gq, g_q);
    float* gk;  cudaGetSymbolAddress((void**)&gk, g_k);
    float* gv;  cudaGetSymbolAddress((void**)&gv, g_v);
    float* gao; cudaGetSymbolAddress((void**)&gao, g_ao);
    float* gxr; cudaGetSymbolAddress((void**)&gxr, g_xr);
    float* gwq; cudaGetSymbolAddress((void**)&gwq, g_wq);
    float* gwk; cudaGetSymbolAddress((void**)&gwk, g_wk);
    float* gwv; cudaGetSymbolAddress((void**)&gwv, g_wv);
    float* gwo; cudaGetSymbolAddress((void**)&gwo, g_wo);

    static bool attr_set = false;
    if (!attr_set) {
        cudaFuncSetAttribute(attn_mma,
                             cudaFuncAttributeMaxDynamicSharedMemorySize,
                             ATTN_SMEM);
        cudaFuncSetAttribute(gemm_tf32,
                             cudaFuncAttributeMaxDynamicSharedMemorySize,
                             GEMM_SMEM);
        attr_set = true;
    }

    // Pre-round inputs/weights to tf32.
    pre_round_x<<<(cM * cC) / (256 * 4), 256>>>(x, gxr);
    pre_round_w<<<dim3((cInner * cC) / (256 * 4), 1, 4), 256>>>(
        Wq, Wk, Wv, Wo, gwq, gwk, gwv, gwo);

    // Fused QKV projections (epilogue pre-rounds; q pre-scaled by SCALE).
    gemm_tf32<<<dim3(cInner / 128, cM / 128, 3), 256, GEMM_SMEM>>>(
        gxr, gwq, gwk, gwv, gq, gk, gv, nullptr, cM, cInner, cC, SCALE, 1);

    attn_mma<<<dim3(16, 8, 8), 128, ATTN_SMEM>>>(ctx);

    // Output projection (raw fragments; bias added fp32).
    gemm_tf32<<<dim3(cC / 128, cM / 128, 1), 256, GEMM_SMEM>>>(
        gao, gwo, gwo, gwo, out, out, out, bo, cM, cC, cInner, 1.0f, 0);
}

// round 13
// speedup vs baseline: 1.3894x; 1.3894x over previous
#include <cuda_runtime.h>
#include <cuda_bf16.h>
#include <cstdint>

// Problem constants
constexpr int cB = 8;
constexpr int cN = 1024;
constexpr int cC = 640;
constexpr int cH = 8;
constexpr int cD = 80;
constexpr int cR = 3;
constexpr int cInner = cH * cD;        // 640
constexpr int cM = cB * cN;            // 8192
constexpr float SCALE = 0.11180339887498949f;  // 80^-0.5

// Scratch
__device__ float g_q[cM * cInner];
__device__ float g_k[cM * cInner];
__device__ float g_v[cM * cInner];
__device__ float g_ao[cM * cInner];
__device__ float g_xr[cM * cC];            // pre-rounded x
__device__ float g_wq[cInner * cC];        // pre-rounded weights
__device__ float g_wk[cInner * cC];
__device__ float g_wv[cInner * cC];
__device__ float g_wo[cC * cInner];

// ---------------------------------------------------------------------------
// helpers
// ---------------------------------------------------------------------------
__device__ __forceinline__ uint32_t smem_u32(const void* p) {
    uint32_t a;
    asm("{ .reg .u64 t; cvta.to.shared.u64 t, %1; cvt.u32.u64 %0, t; }"
        : "=r"(a) : "l"(p));
    return a;
}
__device__ __forceinline__ uint32_t tf32r(float x) {
    uint32_t r;
    asm("cvt.rna.tf32.f32 %0, %1;" : "=r"(r) : "f"(x));
    return r;
}
__device__ __forceinline__ float tf32rf(float x) {
    return __uint_as_float(tf32r(x));
}
__device__ __forceinline__ void mma_tf32(float* c, const uint32_t* a,
                                         uint32_t b0, uint32_t b1) {
    asm volatile(
        "mma.sync.aligned.m16n8k8.row.col.f32.tf32.tf32.f32 "
        "{%0,%1,%2,%3}, {%4,%5,%6,%7}, {%8,%9}, {%0,%1,%2,%3};"
        : "+f"(c[0]), "+f"(c[1]), "+f"(c[2]), "+f"(c[3])
        : "r"(a[0]), "r"(a[1]), "r"(a[2]), "r"(a[3]), "r"(b0), "r"(b1));
}
__device__ __forceinline__ void cp_async16(uint32_t dst, const void* src) {
    asm volatile("cp.async.ca.shared.global [%0], [%1], 16;" :: "r"(dst), "l"(src));
}
__device__ __forceinline__ void cp_commit() {
    asm volatile("cp.async.commit_group;" ::: "memory");
}
template <int N>
__device__ __forceinline__ void cp_wait() {
    asm volatile("cp.async.wait_group %0;" :: "n"(N) : "memory");
}

// ---------------------------------------------------------------------------
// Pre-round kernels (remove all CVT from GEMM hot loops).
// ---------------------------------------------------------------------------
__global__ void pre_round_x(const float* __restrict__ s, float* __restrict__ d) {
    const int i = (blockIdx.x * 256 + threadIdx.x) * 4;
    float4 v = *(const float4*)(s + i);
    *(float4*)(d + i) = make_float4(tf32rf(v.x), tf32rf(v.y), tf32rf(v.z), tf32rf(v.w));
}
__global__ void pre_round_w(const float* __restrict__ s0, const float* __restrict__ s1,
                            const float* __restrict__ s2, const float* __restrict__ s3,
                            float* __restrict__ d0, float* __restrict__ d1,
                            float* __restrict__ d2, float* __restrict__ d3) {
    const int z = blockIdx.z;
    const float* s = (z == 0) ? s0 : (z == 1) ? s1 : (z == 2) ? s2 : s3;
    float* d = (z == 0) ? d0 : (z == 1) ? d1 : (z == 2) ? d2 : d3;
    const int i = (blockIdx.x * 256 + threadIdx.x) * 4;
    float4 v = *(const float4*)(s + i);
    *(float4*)(d + i) = make_float4(tf32rf(v.x), tf32rf(v.y), tf32rf(v.z), tf32rf(v.w));
}

// ---------------------------------------------------------------------------
// tf32 GEMM, cp.async double-buffered, pre-rounded inputs (raw LDS frags).
// gridDim.z fuses up to 3 (B, C) pairs.  doRound: epilogue tf32rf(val*pm).
// (unchanged — round-10 proven)
// ---------------------------------------------------------------------------
constexpr int GP2  = 36;
constexpr int GBUF = 128 * GP2;
constexpr int GEMM_SMEM = 4 * GBUF * 4;     // 73728 B

__global__ __launch_bounds__(256, 2) void gemm_tf32(
    const float* __restrict__ A,
    const float* __restrict__ B0, const float* __restrict__ B1,
    const float* __restrict__ B2,
    float* __restrict__ C0, float* __restrict__ C1, float* __restrict__ C2,
    const float* __restrict__ bias,
    int M, int Nc, int K, float pm, int doRound)
{
    extern __shared__ float gsm[];
    float* As = gsm;
    float* Bs = gsm + 2 * GBUF;

    const int z = blockIdx.z;
    const float* Bm = (z == 0) ? B0 : (z == 1) ? B1 : B2;
    float* C = (z == 0) ? C0 : (z == 1) ? C1 : C2;
    const float pmz = (z == 0) ? pm : 1.0f;

    const int tid  = threadIdx.x;
    const int wid  = tid >> 5;
    const int lane = tid & 31;
    const int gid  = lane >> 2;
    const int tig  = lane & 3;
    const int wm   = (wid & 1) * 64;
    const int wn   = (wid >> 1) * 32;

    const int srow = tid >> 1;
    const int skc  = (tid & 1) * 16;

    const float* Ap = A  + (size_t)(blockIdx.y * 128 + srow) * K + skc;
    const float* Bp = Bm + (size_t)(blockIdx.x * 128 + srow) * K + skc;
    const uint32_t sA = smem_u32(As) + (srow * GP2 + skc) * 4;
    const uint32_t sB = smem_u32(Bs) + (srow * GP2 + skc) * 4;
    const uint32_t bufB = GBUF * 4;

    float acc[4][4][4];
#pragma unroll
    for (int mi = 0; mi < 4; mi++)
#pragma unroll
        for (int nj = 0; nj < 4; nj++)
#pragma unroll
            for (int j = 0; j < 4; j++) acc[mi][nj][j] = 0.f;

    const int nk = K >> 5;

#pragma unroll
    for (int i = 0; i < 4; i++) {
        cp_async16(sA + i * 16, Ap + i * 4);
        cp_async16(sB + i * 16, Bp + i * 4);
    }
    cp_commit();

#pragma unroll 1
    for (int t = 0; t < nk; t++) {
        if (t + 1 < nk) {
            const uint32_t bo = (uint32_t)((t + 1) & 1) * bufB;
            const float* ap = Ap + (t + 1) * 32;
            const float* bp = Bp + (t + 1) * 32;
#pragma unroll
            for (int i = 0; i < 4; i++) {
                cp_async16(sA + bo + i * 16, ap + i * 4);
                cp_async16(sB + bo + i * 16, bp + i * 4);
            }
            cp_commit();
            cp_wait<1>();
        } else {
            cp_wait<0>();
        }
        __syncthreads();

        const float* Ab = As + (t & 1) * GBUF;
        const float* Bb = Bs + (t & 1) * GBUF;

#pragma unroll
        for (int ks = 0; ks < 4; ks++) {
            uint32_t af[4][4];
#pragma unroll
            for (int mi = 0; mi < 4; mi++) {
                const float* p0 = Ab + (wm + mi * 16 + gid) * GP2 + ks * 8 + tig;
                af[mi][0] = __float_as_uint(p0[0]);
                af[mi][1] = __float_as_uint(p0[8 * GP2]);
                af[mi][2] = __float_as_uint(p0[4]);
                af[mi][3] = __float_as_uint(p0[8 * GP2 + 4]);
            }
#pragma unroll
            for (int nj = 0; nj < 4; nj++) {
                const float* p = Bb + (wn + nj * 8 + gid) * GP2 + ks * 8 + tig;
                const uint32_t b0 = __float_as_uint(p[0]);
                const uint32_t b1 = __float_as_uint(p[4]);
#pragma unroll
                for (int mi = 0; mi < 4; mi++)
                    mma_tf32(acc[mi][nj], af[mi], b0, b1);
            }
        }
        __syncthreads();
    }

#pragma unroll
    for (int nj = 0; nj < 4; nj++) {
        const int col = blockIdx.x * 128 + wn + nj * 8 + tig * 2;
        const float ba0 = bias ? bias[col]     : 0.f;
        const float ba1 = bias ? bias[col + 1] : 0.f;
#pragma unroll
        for (int mi = 0; mi < 4; mi++) {
            const int row = blockIdx.y * 128 + wm + mi * 16 + gid;
            float* cp = C + (size_t)row * Nc + col;
            float v00 = acc[mi][nj][0] + ba0;
            float v01 = acc[mi][nj][1] + ba1;
            float v10 = acc[mi][nj][2] + ba0;
            float v11 = acc[mi][nj][3] + ba1;
            if (doRound) {
                v00 = tf32rf(v00 * pmz); v01 = tf32rf(v01 * pmz);
                v10 = tf32rf(v10 * pmz); v11 = tf32rf(v11 * pmz);
            }
            *(float2*)cp = make_float2(v00, v01);
            *(float2*)(cp + (size_t)8 * Nc) = make_float2(v10, v11);
        }
    }
}

// ---------------------------------------------------------------------------
// Flash attention, mma.sync tf32.  EXACT round-10 config (128q x 128k,
// 256 threads, sync staging) with ONE change: the key rows of K are stored
// PERMUTED within each 8-group, pi(k) = 2(k&3) + ((k>>2)&1).  Then S's
// column position p holds key kappa(p) with kappa(2t)=t, kappa(2t+1)=t+4,
// which makes the S C-fragment slots EXACTLY the PV A-fragment in natural
// key order:  pa = {cvt(s0), cvt(s2), cvt(s1), cvt(s3)}.  The entire
// 128-SHFL/tile P-conversion block is deleted.  V layout, S-loop
// addressing, softmax (permutation-invariant) all unchanged.
// Smem: Qs[128][84] + Ks[128][88] + Vs[128][88] = 133120 B.
// ---------------------------------------------------------------------------
constexpr int QSP = 84;
constexpr int KSP = 88;                   // %32==24: LDS.64 frags conflict-free
constexpr int VSP = 88;
constexpr int SM_KS = 128 * QSP;          // word offsets
constexpr int SM_VS = SM_KS + 128 * KSP;
constexpr int ATTN_SMEM = (SM_VS + 128 * VSP) * 4;   // 133120 bytes

__global__ __launch_bounds__(256, 1) void attn_mma(const int* __restrict__ ctx)
{
    extern __shared__ float sm[];
    float* Qs = sm;
    float* Ks = sm + SM_KS;
    float* Vs = sm + SM_VS;

    const int tid  = threadIdx.x;
    const int wid  = tid >> 5;
    const int lane = tid & 31;
    const int gid  = lane >> 2;
    const int tig  = lane & 3;
    const int m0   = wid * 16;

    const int qt = blockIdx.x, h = blockIdx.y, b = blockIdx.z;

    const int r0 = tid >> 1;           // 0..127 (staged key/query row)
    const int d0 = (tid & 1) * 40;     // 0/40
    // K row permutation within 8-groups: position pi(k) holds key k
    const int rK = (r0 & ~7) + 2 * (r0 & 3) + ((r0 >> 2) & 1);

    const int frame0 = ctx[b * cR + 0];
    const int frame1 = ctx[b * cR + 1];
    const int frame2 = ctx[b * cR + 2];

    // ---- stage Q (pre-scaled, pre-rounded: pure copy) ----
    {
        const float* qp = g_q + (size_t)(b * cN + qt * 128 + r0) * cInner + h * cD + d0;
        float* qs = Qs + r0 * QSP + d0;
#pragma unroll
        for (int i = 0; i < 10; i++)
            *(float4*)(qs + i * 4) = *(const float4*)(qp + i * 4);
    }
    __syncthreads();

    // ---- Q A-fragments in registers (reused for all 24 KV tiles) ----
    uint32_t qa[10][4];
#pragma unroll
    for (int k = 0; k < 10; k++) {
        qa[k][0] = __float_as_uint(Qs[(m0 + gid) * QSP + k * 8 + tig]);
        qa[k][1] = __float_as_uint(Qs[(m0 + gid + 8) * QSP + k * 8 + tig]);
        qa[k][2] = __float_as_uint(Qs[(m0 + gid) * QSP + k * 8 + tig + 4]);
        qa[k][3] = __float_as_uint(Qs[(m0 + gid + 8) * QSP + k * 8 + tig + 4]);
    }

    float o[10][4];
#pragma unroll
    for (int n = 0; n < 10; n++)
#pragma unroll
        for (int j = 0; j < 4; j++) o[n][j] = 0.f;
    float llo = 0.f, lhi = 0.f;      // lane-partial row sums

#pragma unroll 1
    for (int t = 0; t < 24; t++) {
        __syncthreads();   // prev tile's readers done before overwrite

        // ---- stage K (d-interleaved cols, pi-permuted rows) and V ----
        {
            const int frame = (t >> 3) == 0 ? frame0 : (t >> 3) == 1 ? frame1 : frame2;
            const int kb = (t * 128) & (cN - 1);
            const size_t gof = (size_t)(frame * cN + kb + r0) * cInner + h * cD;
            const float* kp = g_k + gof;
            const float* vp = g_v + gof;
            float* ks = Ks + rK * KSP;
            float* vs = Vs + r0 * VSP;
#pragma unroll
            for (int g = 0; g < 5; g++) {
                const int base = d0 + g * 8;
                float4 ka = *(const float4*)(kp + base);
                float4 kc = *(const float4*)(kp + base + 4);
                *(float4*)(ks + base)     = make_float4(ka.x, kc.x, ka.y, kc.y);
                *(float4*)(ks + base + 4) = make_float4(ka.z, kc.z, ka.w, kc.w);
                *(float4*)(vs + base)     = *(const float4*)(vp + base);
                *(float4*)(vs + base + 4) = *(const float4*)(vp + base + 4);
            }
        }
        __syncthreads();

        // ---- S = Q K^T : 16 n-tiles x 10 k-steps, B-pairs via LDS.64 ----
        // (column position p of each n-tile = key kappa(p); softmax is
        //  permutation-invariant, PV consumes positions directly)
        float s[16][4];
#pragma unroll
        for (int n = 0; n < 16; n++)
#pragma unroll
            for (int j = 0; j < 4; j++) s[n][j] = 0.f;

#pragma unroll
        for (int n = 0; n < 16; n++) {
            const float* krow = Ks + (n * 8 + gid) * KSP + 2 * tig;
#pragma unroll
            for (int k = 0; k < 10; k++) {
                float2 bb = *(const float2*)(krow + k * 8);
                mma_tf32(s[n], qa[k], __float_as_uint(bb.x), __float_as_uint(bb.y));
            }
        }

        // ---- softmax numerator (no max subtraction; logits bounded) ----
        float rs0 = 0.f, rs1 = 0.f;
#pragma unroll
        for (int n = 0; n < 16; n++) {
            s[n][0] = __expf(s[n][0]); rs0 += s[n][0];
            s[n][1] = __expf(s[n][1]); rs0 += s[n][1];
            s[n][2] = __expf(s[n][2]); rs1 += s[n][2];
            s[n][3] = __expf(s[n][3]); rs1 += s[n][3];
        }
        llo += rs0;
        lhi += rs1;

        // ---- O += P V : 16 k-tiles x 10 n-tiles.
        //      C-frag slots ARE the A-frag (key-permuted S): no shuffles. ----
#pragma unroll
        for (int kt = 0; kt < 16; kt++) {
            uint32_t pa[4];
            pa[0] = tf32r(s[kt][0]);   // (row gid,   key kt*8+tig)
            pa[1] = tf32r(s[kt][2]);   // (row gid+8, key kt*8+tig)
            pa[2] = tf32r(s[kt][1]);   // (row gid,   key kt*8+tig+4)
            pa[3] = tf32r(s[kt][3]);   // (row gid+8, key kt*8+tig+4)

            const float* vrow0 = Vs + (kt * 8 + tig) * VSP + gid;
            const float* vrow1 = Vs + (kt * 8 + tig + 4) * VSP + gid;
#pragma unroll
            for (int n = 0; n < 10; n++) {
                uint32_t b0 = __float_as_uint(vrow0[n * 8]);
                uint32_t b1 = __float_as_uint(vrow1[n * 8]);
                mma_tf32(o[n], pa, b0, b1);
            }
        }
    }

    // ---- epilogue: reduce row sums once, normalize, pre-round ----
    llo += __shfl_xor_sync(0xffffffffu, llo, 1);
    llo += __shfl_xor_sync(0xffffffffu, llo, 2);
    lhi += __shfl_xor_sync(0xffffffffu, lhi, 1);
    lhi += __shfl_xor_sync(0xffffffffu, lhi, 2);
    const float inv0 = 1.f / llo;
    const float inv1 = 1.f / lhi;
    float* op0 = g_ao + (size_t)(b * cN + qt * 128 + m0 + gid) * cInner + h * cD;
    float* op1 = op0 + (size_t)8 * cInner;
#pragma unroll
    for (int n = 0; n < 10; n++) {
        *(float2*)(op0 + n * 8 + tig * 2) =
            make_float2(tf32rf(o[n][0] * inv0), tf32rf(o[n][1] * inv0));
        *(float2*)(op1 + n * 8 + tig * 2) =
            make_float2(tf32rf(o[n][2] * inv1), tf32rf(o[n][3] * inv1));
    }
}

// ---------------------------------------------------------------------------
extern "C" void kernel_launch(void* const* d_in, const int* in_sizes, int n_in,
                              void* d_out, int out_size)
{
    const float* x   = (const float*)d_in[0];
    const float* Wq  = (const float*)d_in[1];
    const float* Wk  = (const float*)d_in[2];
    const float* Wv  = (const float*)d_in[3];
    const float* Wo  = (const float*)d_in[4];
    const float* bo  = (const float*)d_in[5];
    const int*   ctx = (const int*)d_in[6];
    float* out = (float*)d_out;

    float* gq;  cudaGetSymbolAddress((void**)&gq, g_q);
    float* gk;  cudaGetSymbolAddress((void**)&gk, g_k);
    float* gv;  cudaGetSymbolAddress((void**)&gv, g_v);
    float* gao; cudaGetSymbolAddress((void**)&gao, g_ao);
    float* gxr; cudaGetSymbolAddress((void**)&gxr, g_xr);
    float* gwq; cudaGetSymbolAddress((void**)&gwq, g_wq);
    float* gwk; cudaGetSymbolAddress((void**)&gwk, g_wk);
    float* gwv; cudaGetSymbolAddress((void**)&gwv, g_wv);
    float* gwo; cudaGetSymbolAddress((void**)&gwo, g_wo);

    static bool attr_set = false;
    if (!attr_set) {
        cudaFuncSetAttribute(attn_mma,
                             cudaFuncAttributeMaxDynamicSharedMemorySize,
                             ATTN_SMEM);
        cudaFuncSetAttribute(gemm_tf32,
                             cudaFuncAttributeMaxDynamicSharedMemorySize,
                             GEMM_SMEM);
        attr_set = true;
    }

    // Pre-round inputs/weights to tf32.
    pre_round_x<<<(cM * cC) / (256 * 4), 256>>>(x, gxr);
    pre_round_w<<<dim3((cInner * cC) / (256 * 4), 1, 4), 256>>>(
        Wq, Wk, Wv, Wo, gwq, gwk, gwv, gwo);

    // Fused QKV projections (epilogue pre-rounds; q pre-scaled by SCALE).
    gemm_tf32<<<dim3(cInner / 128, cM / 128, 3), 256, GEMM_SMEM>>>(
        gxr, gwq, gwk, gwv, gq, gk, gv, nullptr, cM, cInner, cC, SCALE, 1);

    attn_mma<<<dim3(8, 8, 8), 256, ATTN_SMEM>>>(ctx);

    // Output projection (raw fragments; bias added fp32).
    gemm_tf32<<<dim3(cC / 128, cM / 128, 1), 256, GEMM_SMEM>>>(
        gao, gwo, gwo, gwo, out, out, out, bo, cM, cC, cInner, 1.0f, 0);
}

// round 14
// speedup vs baseline: 1.4627x; 1.0527x over previous
#include <cuda_runtime.h>
#include <cuda_bf16.h>
#include <cstdint>

// Problem constants
constexpr int cB = 8;
constexpr int cN = 1024;
constexpr int cC = 640;
constexpr int cH = 8;
constexpr int cD = 80;
constexpr int cR = 3;
constexpr int cInner = cH * cD;        // 640
constexpr int cM = cB * cN;            // 8192
constexpr float SCALE = 0.11180339887498949f;       // 80^-0.5
// SCALE * log2(e): logits emerge in base-2 domain -> softmax uses raw ex2
constexpr float SCALE_L2E = 0.16129821801934495f;

// Scratch
__device__ float g_q[cM * cInner];
__device__ float g_k[cM * cInner];
__device__ float g_v[cM * cInner];
__device__ float g_ao[cM * cInner];
__device__ float g_xr[cM * cC];            // pre-rounded x
__device__ float g_wq[cInner * cC];        // pre-rounded weights
__device__ float g_wk[cInner * cC];
__device__ float g_wv[cInner * cC];
__device__ float g_wo[cC * cInner];

// ---------------------------------------------------------------------------
// helpers
// ---------------------------------------------------------------------------
__device__ __forceinline__ uint32_t smem_u32(const void* p) {
    uint32_t a;
    asm("{ .reg .u64 t; cvta.to.shared.u64 t, %1; cvt.u32.u64 %0, t; }"
        : "=r"(a) : "l"(p));
    return a;
}
__device__ __forceinline__ uint32_t tf32r(float x) {
    uint32_t r;
    asm("cvt.rna.tf32.f32 %0, %1;" : "=r"(r) : "f"(x));
    return r;
}
__device__ __forceinline__ float tf32rf(float x) {
    return __uint_as_float(tf32r(x));
}
__device__ __forceinline__ float ex2(float x) {
    float r;
    asm("ex2.approx.f32 %0, %1;" : "=f"(r) : "f"(x));
    return r;
}
__device__ __forceinline__ void mma_tf32(float* c, const uint32_t* a,
                                         uint32_t b0, uint32_t b1) {
    asm volatile(
        "mma.sync.aligned.m16n8k8.row.col.f32.tf32.tf32.f32 "
        "{%0,%1,%2,%3}, {%4,%5,%6,%7}, {%8,%9}, {%0,%1,%2,%3};"
        : "+f"(c[0]), "+f"(c[1]), "+f"(c[2]), "+f"(c[3])
        : "r"(a[0]), "r"(a[1]), "r"(a[2]), "r"(a[3]), "r"(b0), "r"(b1));
}
__device__ __forceinline__ void cp_async16(uint32_t dst, const void* src) {
    asm volatile("cp.async.ca.shared.global [%0], [%1], 16;" :: "r"(dst), "l"(src));
}
__device__ __forceinline__ void cp_commit() {
    asm volatile("cp.async.commit_group;" ::: "memory");
}
template <int N>
__device__ __forceinline__ void cp_wait() {
    asm volatile("cp.async.wait_group %0;" :: "n"(N) : "memory");
}

// ---------------------------------------------------------------------------
// Pre-round kernels (remove all CVT from GEMM hot loops).
// ---------------------------------------------------------------------------
__global__ void pre_round_x(const float* __restrict__ s, float* __restrict__ d) {
    const int i = (blockIdx.x * 256 + threadIdx.x) * 4;
    float4 v = *(const float4*)(s + i);
    *(float4*)(d + i) = make_float4(tf32rf(v.x), tf32rf(v.y), tf32rf(v.z), tf32rf(v.w));
}
__global__ void pre_round_w(const float* __restrict__ s0, const float* __restrict__ s1,
                            const float* __restrict__ s2, const float* __restrict__ s3,
                            float* __restrict__ d0, float* __restrict__ d1,
                            float* __restrict__ d2, float* __restrict__ d3) {
    const int z = blockIdx.z;
    const float* s = (z == 0) ? s0 : (z == 1) ? s1 : (z == 2) ? s2 : s3;
    float* d = (z == 0) ? d0 : (z == 1) ? d1 : (z == 2) ? d2 : d3;
    const int i = (blockIdx.x * 256 + threadIdx.x) * 4;
    float4 v = *(const float4*)(s + i);
    *(float4*)(d + i) = make_float4(tf32rf(v.x), tf32rf(v.y), tf32rf(v.z), tf32rf(v.w));
}

// ---------------------------------------------------------------------------
// tf32 GEMM, cp.async double-buffered, pre-rounded inputs (raw LDS frags).
// gridDim.z fuses up to 3 (B, C) pairs.  doRound: epilogue tf32rf(val*pm).
// (unchanged — round-10 proven)
// ---------------------------------------------------------------------------
constexpr int GP2  = 36;
constexpr int GBUF = 128 * GP2;
constexpr int GEMM_SMEM = 4 * GBUF * 4;     // 73728 B

__global__ __launch_bounds__(256, 2) void gemm_tf32(
    const float* __restrict__ A,
    const float* __restrict__ B0, const float* __restrict__ B1,
    const float* __restrict__ B2,
    float* __restrict__ C0, float* __restrict__ C1, float* __restrict__ C2,
    const float* __restrict__ bias,
    int M, int Nc, int K, float pm, int doRound)
{
    extern __shared__ float gsm[];
    float* As = gsm;
    float* Bs = gsm + 2 * GBUF;

    const int z = blockIdx.z;
    const float* Bm = (z == 0) ? B0 : (z == 1) ? B1 : B2;
    float* C = (z == 0) ? C0 : (z == 1) ? C1 : C2;
    const float pmz = (z == 0) ? pm : 1.0f;

    const int tid  = threadIdx.x;
    const int wid  = tid >> 5;
    const int lane = tid & 31;
    const int gid  = lane >> 2;
    const int tig  = lane & 3;
    const int wm   = (wid & 1) * 64;
    const int wn   = (wid >> 1) * 32;

    const int srow = tid >> 1;
    const int skc  = (tid & 1) * 16;

    const float* Ap = A  + (size_t)(blockIdx.y * 128 + srow) * K + skc;
    const float* Bp = Bm + (size_t)(blockIdx.x * 128 + srow) * K + skc;
    const uint32_t sA = smem_u32(As) + (srow * GP2 + skc) * 4;
    const uint32_t sB = smem_u32(Bs) + (srow * GP2 + skc) * 4;
    const uint32_t bufB = GBUF * 4;

    float acc[4][4][4];
#pragma unroll
    for (int mi = 0; mi < 4; mi++)
#pragma unroll
        for (int nj = 0; nj < 4; nj++)
#pragma unroll
            for (int j = 0; j < 4; j++) acc[mi][nj][j] = 0.f;

    const int nk = K >> 5;

#pragma unroll
    for (int i = 0; i < 4; i++) {
        cp_async16(sA + i * 16, Ap + i * 4);
        cp_async16(sB + i * 16, Bp + i * 4);
    }
    cp_commit();

#pragma unroll 1
    for (int t = 0; t < nk; t++) {
        if (t + 1 < nk) {
            const uint32_t bo = (uint32_t)((t + 1) & 1) * bufB;
            const float* ap = Ap + (t + 1) * 32;
            const float* bp = Bp + (t + 1) * 32;
#pragma unroll
            for (int i = 0; i < 4; i++) {
                cp_async16(sA + bo + i * 16, ap + i * 4);
                cp_async16(sB + bo + i * 16, bp + i * 4);
            }
            cp_commit();
            cp_wait<1>();
        } else {
            cp_wait<0>();
        }
        __syncthreads();

        const float* Ab = As + (t & 1) * GBUF;
        const float* Bb = Bs + (t & 1) * GBUF;

#pragma unroll
        for (int ks = 0; ks < 4; ks++) {
            uint32_t af[4][4];
#pragma unroll
            for (int mi = 0; mi < 4; mi++) {
                const float* p0 = Ab + (wm + mi * 16 + gid) * GP2 + ks * 8 + tig;
                af[mi][0] = __float_as_uint(p0[0]);
                af[mi][1] = __float_as_uint(p0[8 * GP2]);
                af[mi][2] = __float_as_uint(p0[4]);
                af[mi][3] = __float_as_uint(p0[8 * GP2 + 4]);
            }
#pragma unroll
            for (int nj = 0; nj < 4; nj++) {
                const float* p = Bb + (wn + nj * 8 + gid) * GP2 + ks * 8 + tig;
                const uint32_t b0 = __float_as_uint(p[0]);
                const uint32_t b1 = __float_as_uint(p[4]);
#pragma unroll
                for (int mi = 0; mi < 4; mi++)
                    mma_tf32(acc[mi][nj], af[mi], b0, b1);
            }
        }
        __syncthreads();
    }

#pragma unroll
    for (int nj = 0; nj < 4; nj++) {
        const int col = blockIdx.x * 128 + wn + nj * 8 + tig * 2;
        const float ba0 = bias ? bias[col]     : 0.f;
        const float ba1 = bias ? bias[col + 1] : 0.f;
#pragma unroll
        for (int mi = 0; mi < 4; mi++) {
            const int row = blockIdx.y * 128 + wm + mi * 16 + gid;
            float* cp = C + (size_t)row * Nc + col;
            float v00 = acc[mi][nj][0] + ba0;
            float v01 = acc[mi][nj][1] + ba1;
            float v10 = acc[mi][nj][2] + ba0;
            float v11 = acc[mi][nj][3] + ba1;
            if (doRound) {
                v00 = tf32rf(v00 * pmz); v01 = tf32rf(v01 * pmz);
                v10 = tf32rf(v10 * pmz); v11 = tf32rf(v11 * pmz);
            }
            *(float2*)cp = make_float2(v00, v01);
            *(float2*)(cp + (size_t)8 * Nc) = make_float2(v10, v11);
        }
    }
}

// ---------------------------------------------------------------------------
// Flash attention, mma.sync tf32.  r13 config plus two deletions:
//  (a) V transposed+interleaved: V[key>>3][d][pi(key)], group stride 656
//      words (==16 mod 32), +328-word offset for the d>=40 half.  The same
//      pi that permutes K rows makes PV B-pairs (key tig, tig+4) ADJACENT
//      -> PV loop does 160 LDS.64 instead of 320 LDS.32.  Staging is 40
//      scatter STS.32 (verified all-32-banks per instruction).
//  (b) Q pre-scaled by SCALE*log2(e) in the producer -> logits in base-2
//      domain -> softmax = raw ex2.approx (no FMUL prelude).
// K: pi-permuted rows + d-interleaved cols (r13).  No-max softmax.
// Smem: Qs[128][84] + Ks[128][88] + Vt[16][656] = 130048 B.
// ---------------------------------------------------------------------------
constexpr int QSP = 84;
constexpr int KSP = 88;                   // %32==24: LDS.64 frags conflict-free
constexpr int VGS = 656;                  // V group stride (%32==16)
constexpr int SM_KS = 128 * QSP;          // word offsets
constexpr int SM_VS = SM_KS + 128 * KSP;
constexpr int ATTN_SMEM = (SM_VS + 16 * VGS) * 4;   // 130048 bytes

__global__ __launch_bounds__(256, 1) void attn_mma(const int* __restrict__ ctx)
{
    extern __shared__ float sm[];
    float* Qs = sm;
    float* Ks = sm + SM_KS;
    float* Vt = sm + SM_VS;

    const int tid  = threadIdx.x;
    const int wid  = tid >> 5;
    const int lane = tid & 31;
    const int gid  = lane >> 2;
    const int tig  = lane & 3;
    const int m0   = wid * 16;

    const int qt = blockIdx.x, h = blockIdx.y, b = blockIdx.z;

    const int r0 = tid >> 1;           // 0..127 (staged key/query row)
    const int d0 = (tid & 1) * 40;     // 0/40
    // K row permutation within 8-groups: position pi(k) holds key k
    const int rK = (r0 & ~7) + 2 * (r0 & 3) + ((r0 >> 2) & 1);
    // V staging destination (word offset): group*656 + d-half*328 + pi(key)
    const int vstoff = (r0 >> 3) * VGS + ((tid & 1) ? 328 : 0)
                     + 2 * (r0 & 3) + ((r0 >> 2) & 1);

    const int frame0 = ctx[b * cR + 0];
    const int frame1 = ctx[b * cR + 1];
    const int frame2 = ctx[b * cR + 2];

    // ---- stage Q (pre-scaled by SCALE*log2e, pre-rounded: pure copy) ----
    {
        const float* qp = g_q + (size_t)(b * cN + qt * 128 + r0) * cInner + h * cD + d0;
        float* qs = Qs + r0 * QSP + d0;
#pragma unroll
        for (int i = 0; i < 10; i++)
            *(float4*)(qs + i * 4) = *(const float4*)(qp + i * 4);
    }
    __syncthreads();

    // ---- Q A-fragments in registers (reused for all 24 KV tiles) ----
    uint32_t qa[10][4];
#pragma unroll
    for (int k = 0; k < 10; k++) {
        qa[k][0] = __float_as_uint(Qs[(m0 + gid) * QSP + k * 8 + tig]);
        qa[k][1] = __float_as_uint(Qs[(m0 + gid + 8) * QSP + k * 8 + tig]);
        qa[k][2] = __float_as_uint(Qs[(m0 + gid) * QSP + k * 8 + tig + 4]);
        qa[k][3] = __float_as_uint(Qs[(m0 + gid + 8) * QSP + k * 8 + tig + 4]);
    }

    float o[10][4];
#pragma unroll
    for (int n = 0; n < 10; n++)
#pragma unroll
        for (int j = 0; j < 4; j++) o[n][j] = 0.f;
    float llo = 0.f, lhi = 0.f;      // lane-partial row sums

#pragma unroll 1
    for (int t = 0; t < 24; t++) {
        __syncthreads();   // prev tile's readers done before overwrite

        // ---- stage K (d-interleaved, pi rows) and V (transposed scatter) ----
        {
            const int frame = (t >> 3) == 0 ? frame0 : (t >> 3) == 1 ? frame1 : frame2;
            const int kb = (t * 128) & (cN - 1);
            const size_t gof = (size_t)(frame * cN + kb + r0) * cInner + h * cD;
            const float* kp = g_k + gof;
            const float* vp = g_v + gof + d0;
            float* ks = Ks + rK * KSP;
            float* vd = Vt + vstoff;
#pragma unroll
            for (int g = 0; g < 5; g++) {
                const int base = d0 + g * 8;
                float4 ka = *(const float4*)(kp + base);
                float4 kc = *(const float4*)(kp + base + 4);
                *(float4*)(ks + base)     = make_float4(ka.x, kc.x, ka.y, kc.y);
                *(float4*)(ks + base + 4) = make_float4(ka.z, kc.z, ka.w, kc.w);
            }
#pragma unroll
            for (int i = 0; i < 10; i++) {
                float4 vv = *(const float4*)(vp + i * 4);
                vd[(i * 4 + 0) * 8] = vv.x;
                vd[(i * 4 + 1) * 8] = vv.y;
                vd[(i * 4 + 2) * 8] = vv.z;
                vd[(i * 4 + 3) * 8] = vv.w;
            }
        }
        __syncthreads();

        // ---- S = Q K^T : 16 n-tiles x 10 k-steps, B-pairs via LDS.64 ----
        float s[16][4];
#pragma unroll
        for (int n = 0; n < 16; n++)
#pragma unroll
            for (int j = 0; j < 4; j++) s[n][j] = 0.f;

#pragma unroll
        for (int n = 0; n < 16; n++) {
            const float* krow = Ks + (n * 8 + gid) * KSP + 2 * tig;
#pragma unroll
            for (int k = 0; k < 10; k++) {
                float2 bb = *(const float2*)(krow + k * 8);
                mma_tf32(s[n], qa[k], __float_as_uint(bb.x), __float_as_uint(bb.y));
            }
        }

        // ---- softmax numerator: logits are base-2 -> raw ex2.approx ----
        float rs0 = 0.f, rs1 = 0.f;
#pragma unroll
        for (int n = 0; n < 16; n++) {
            s[n][0] = ex2(s[n][0]); rs0 += s[n][0];
            s[n][1] = ex2(s[n][1]); rs0 += s[n][1];
            s[n][2] = ex2(s[n][2]); rs1 += s[n][2];
            s[n][3] = ex2(s[n][3]); rs1 += s[n][3];
        }
        llo += rs0;
        lhi += rs1;

        // ---- O += P V : C-frag slots ARE the A-frag; B-pairs via LDS.64 ----
#pragma unroll
        for (int kt = 0; kt < 16; kt++) {
            uint32_t pa[4];
            pa[0] = tf32r(s[kt][0]);   // (row gid,   key kt*8+tig)
            pa[1] = tf32r(s[kt][2]);   // (row gid+8, key kt*8+tig)
            pa[2] = tf32r(s[kt][1]);   // (row gid,   key kt*8+tig+4)
            pa[3] = tf32r(s[kt][3]);   // (row gid+8, key kt*8+tig+4)

            const float* vg = Vt + kt * VGS + gid * 8 + 2 * tig;
#pragma unroll
            for (int n = 0; n < 10; n++) {
                float2 bb = *(const float2*)(vg + n * 64 + (n >= 5 ? 8 : 0));
                mma_tf32(o[n], pa, __float_as_uint(bb.x), __float_as_uint(bb.y));
            }
        }
    }

    // ---- epilogue: reduce row sums once, normalize, pre-round ----
    llo += __shfl_xor_sync(0xffffffffu, llo, 1);
    llo += __shfl_xor_sync(0xffffffffu, llo, 2);
    lhi += __shfl_xor_sync(0xffffffffu, lhi, 1);
    lhi += __shfl_xor_sync(0xffffffffu, lhi, 2);
    const float inv0 = 1.f / llo;
    const float inv1 = 1.f / lhi;
    float* op0 = g_ao + (size_t)(b * cN + qt * 128 + m0 + gid) * cInner + h * cD;
    float* op1 = op0 + (size_t)8 * cInner;
#pragma unroll
    for (int n = 0; n < 10; n++) {
        *(float2*)(op0 + n * 8 + tig * 2) =
            make_float2(tf32rf(o[n][0] * inv0), tf32rf(o[n][1] * inv0));
        *(float2*)(op1 + n * 8 + tig * 2) =
            make_float2(tf32rf(o[n][2] * inv1), tf32rf(o[n][3] * inv1));
    }
}

// ---------------------------------------------------------------------------
extern "C" void kernel_launch(void* const* d_in, const int* in_sizes, int n_in,
                              void* d_out, int out_size)
{
    const float* x   = (const float*)d_in[0];
    const float* Wq  = (const float*)d_in[1];
    const float* Wk  = (const float*)d_in[2];
    const float* Wv  = (const float*)d_in[3];
    const float* Wo  = (const float*)d_in[4];
    const float* bo  = (const float*)d_in[5];
    const int*   ctx = (const int*)d_in[6];
    float* out = (float*)d_out;

    float* gq;  cudaGetSymbolAddress((void**)&gq, g_q);
    float* gk;  cudaGetSymbolAddress((void**)&gk, g_k);
    float* gv;  cudaGetSymbolAddress((void**)&gv, g_v);
    float* gao; cudaGetSymbolAddress((void**)&gao, g_ao);
    float* gxr; cudaGetSymbolAddress((void**)&gxr, g_xr);
    float* gwq; cudaGetSymbolAddress((void**)&gwq, g_wq);
    float* gwk; cudaGetSymbolAddress((void**)&gwk, g_wk);
    float* gwv; cudaGetSymbolAddress((void**)&gwv, g_wv);
    float* gwo; cudaGetSymbolAddress((void**)&gwo, g_wo);

    static bool attr_set = false;
    if (!attr_set) {
        cudaFuncSetAttribute(attn_mma,
                             cudaFuncAttributeMaxDynamicSharedMemorySize,
                             ATTN_SMEM);
        cudaFuncSetAttribute(gemm_tf32,
                             cudaFuncAttributeMaxDynamicSharedMemorySize,
                             GEMM_SMEM);
        attr_set = true;
    }

    // Pre-round inputs/weights to tf32.
    pre_round_x<<<(cM * cC) / (256 * 4), 256>>>(x, gxr);
    pre_round_w<<<dim3((cInner * cC) / (256 * 4), 1, 4), 256>>>(
        Wq, Wk, Wv, Wo, gwq, gwk, gwv, gwo);

    // Fused QKV projections (epilogue pre-rounds; q pre-scaled by
    // SCALE*log2e so attention softmax is a bare ex2).
    gemm_tf32<<<dim3(cInner / 128, cM / 128, 3), 256, GEMM_SMEM>>>(
        gxr, gwq, gwk, gwv, gq, gk, gv, nullptr, cM, cInner, cC, SCALE_L2E, 1);

    attn_mma<<<dim3(8, 8, 8), 256, ATTN_SMEM>>>(ctx);

    // Output projection (raw fragments; bias added fp32).
    gemm_tf32<<<dim3(cC / 128, cM / 128, 1), 256, GEMM_SMEM>>>(
        gao, gwo, gwo, gwo, out, out, out, bo, cM, cC, cInner, 1.0f, 0);
}

// round 15
// speedup vs baseline: 1.5950x; 1.0905x over previous
#include <cuda_runtime.h>
#include <cuda_bf16.h>
#include <cstdint>

// Problem constants
constexpr int cB = 8;
constexpr int cN = 1024;
constexpr int cC = 640;
constexpr int cH = 8;
constexpr int cD = 80;
constexpr int cR = 3;
constexpr int cInner = cH * cD;        // 640
constexpr int cM = cB * cN;            // 8192
constexpr float SCALE = 0.11180339887498949f;       // 80^-0.5
constexpr float SCALE_L2E = 0.16129821801934495f;   // SCALE * log2(e)

// Scratch
__device__ float g_q[cM * cInner];
__device__ float g_k[cM * cInner];     // attention layout (perm rows, interleaved d)
__device__ float g_v[cM * cInner];     // attention layout [fh][kgroup][d][pi(key)]
__device__ float g_ao[cM * cInner];    // k-interleaved for out-proj
__device__ float g_xr[cM * cC];        // pre-rounded + k-interleaved x
__device__ float g_wq[cInner * cC];    // pre-rounded + k-interleaved weights
__device__ float g_wk[cInner * cC];
__device__ float g_wv[cInner * cC];
__device__ float g_wo[cC * cInner];

// ---------------------------------------------------------------------------
// helpers
// ---------------------------------------------------------------------------
__device__ __forceinline__ uint32_t smem_u32(const void* p) {
    uint32_t a;
    asm("{ .reg .u64 t; cvta.to.shared.u64 t, %1; cvt.u32.u64 %0, t; }"
        : "=r"(a) : "l"(p));
    return a;
}
__device__ __forceinline__ uint32_t tf32r(float x) {
    uint32_t r;
    asm("cvt.rna.tf32.f32 %0, %1;" : "=r"(r) : "f"(x));
    return r;
}
__device__ __forceinline__ float tf32rf(float x) {
    return __uint_as_float(tf32r(x));
}
__device__ __forceinline__ float ex2(float x) {
    float r;
    asm("ex2.approx.f32 %0, %1;" : "=f"(r) : "f"(x));
    return r;
}
__device__ __forceinline__ void mma_tf32(float* c, const uint32_t* a,
                                         uint32_t b0, uint32_t b1) {
    asm volatile(
        "mma.sync.aligned.m16n8k8.row.col.f32.tf32.tf32.f32 "
        "{%0,%1,%2,%3}, {%4,%5,%6,%7}, {%8,%9}, {%0,%1,%2,%3};"
        : "+f"(c[0]), "+f"(c[1]), "+f"(c[2]), "+f"(c[3])
        : "r"(a[0]), "r"(a[1]), "r"(a[2]), "r"(a[3]), "r"(b0), "r"(b1));
}
__device__ __forceinline__ void cp_async16(uint32_t dst, const void* src) {
    asm volatile("cp.async.ca.shared.global [%0], [%1], 16;" :: "r"(dst), "l"(src));
}
__device__ __forceinline__ void cp_commit() {
    asm volatile("cp.async.commit_group;" ::: "memory");
}
template <int N>
__device__ __forceinline__ void cp_wait() {
    asm volatile("cp.async.wait_group %0;" :: "n"(N) : "memory");
}

// ---------------------------------------------------------------------------
// Pre-round + k-interleave kernels.  Within each 8-group of the contiguous
// (k) index: stored[2j] = orig[j], stored[2j+1] = orig[j+4].  Dot products
// are permutation-invariant when BOTH operands use the same layout.
// ---------------------------------------------------------------------------
__global__ void pre_round_x(const float* __restrict__ s, float* __restrict__ d) {
    const int i = (blockIdx.x * 256 + threadIdx.x) * 8;
    float4 a = *(const float4*)(s + i);
    float4 b = *(const float4*)(s + i + 4);
    *(float4*)(d + i) =
        make_float4(tf32rf(a.x), tf32rf(b.x), tf32rf(a.y), tf32rf(b.y));
    *(float4*)(d + i + 4) =
        make_float4(tf32rf(a.z), tf32rf(b.z), tf32rf(a.w), tf32rf(b.w));
}
__global__ void pre_round_w(const float* __restrict__ s0, const float* __restrict__ s1,
                            const float* __restrict__ s2, const float* __restrict__ s3,
                            float* __restrict__ d0, float* __restrict__ d1,
                            float* __restrict__ d2, float* __restrict__ d3) {
    const int z = blockIdx.z;
    const float* s = (z == 0) ? s0 : (z == 1) ? s1 : (z == 2) ? s2 : s3;
    float* d = (z == 0) ? d0 : (z == 1) ? d1 : (z == 2) ? d2 : d3;
    const int i = (blockIdx.x * 256 + threadIdx.x) * 8;
    float4 a = *(const float4*)(s + i);
    float4 b = *(const float4*)(s + i + 4);
    *(float4*)(d + i) =
        make_float4(tf32rf(a.x), tf32rf(b.x), tf32rf(a.y), tf32rf(b.y));
    *(float4*)(d + i + 4) =
        make_float4(tf32rf(a.z), tf32rf(b.z), tf32rf(a.w), tf32rf(b.w));
}

// ---------------------------------------------------------------------------
// tf32 GEMM, cp.async double-buffered.  Inputs are pre-rounded AND
// k-interleaved, so fragment (k, k+4) pairs are single LDS.64 (pitch 40,
// conflict-free: (4*gid+tig) mod 16 distinct per half-warp phase).
// doRound epilogues (QKV launch):
//   z=0 (q): normal rows, val*pm, tf32-rounded  (attention reads plainly)
//   z=1 (k): attention-native: pi-permuted rows + d-interleaved cols
//   z=2 (v): attention-native: [frame*8+h][key>>3][d][pi(key&7)]
// ---------------------------------------------------------------------------
constexpr int GP2  = 40;
constexpr int GBUF = 128 * GP2;
constexpr int GEMM_SMEM = 4 * GBUF * 4;     // 81920 B

__global__ __launch_bounds__(256, 2) void gemm_tf32(
    const float* __restrict__ A,
    const float* __restrict__ B0, const float* __restrict__ B1,
    const float* __restrict__ B2,
    float* __restrict__ C0, float* __restrict__ C1, float* __restrict__ C2,
    const float* __restrict__ bias,
    int M, int Nc, int K, float pm, int doRound)
{
    extern __shared__ float gsm[];
    float* As = gsm;
    float* Bs = gsm + 2 * GBUF;

    const int z = blockIdx.z;
    const float* Bm = (z == 0) ? B0 : (z == 1) ? B1 : B2;
    float* C = (z == 0) ? C0 : (z == 1) ? C1 : C2;

    const int tid  = threadIdx.x;
    const int wid  = tid >> 5;
    const int lane = tid & 31;
    const int gid  = lane >> 2;
    const int tig  = lane & 3;
    const int wm   = (wid & 1) * 64;
    const int wn   = (wid >> 1) * 32;

    const int srow = tid >> 1;
    const int skc  = (tid & 1) * 16;

    const float* Ap = A  + (size_t)(blockIdx.y * 128 + srow) * K + skc;
    const float* Bp = Bm + (size_t)(blockIdx.x * 128 + srow) * K + skc;
    const uint32_t sA = smem_u32(As) + (srow * GP2 + skc) * 4;
    const uint32_t sB = smem_u32(Bs) + (srow * GP2 + skc) * 4;
    const uint32_t bufB = GBUF * 4;

    float acc[4][4][4];
#pragma unroll
    for (int mi = 0; mi < 4; mi++)
#pragma unroll
        for (int nj = 0; nj < 4; nj++)
#pragma unroll
            for (int j = 0; j < 4; j++) acc[mi][nj][j] = 0.f;

    const int nk = K >> 5;

#pragma unroll
    for (int i = 0; i < 4; i++) {
        cp_async16(sA + i * 16, Ap + i * 4);
        cp_async16(sB + i * 16, Bp + i * 4);
    }
    cp_commit();

#pragma unroll 1
    for (int t = 0; t < nk; t++) {
        if (t + 1 < nk) {
            const uint32_t bo = (uint32_t)((t + 1) & 1) * bufB;
            const float* ap = Ap + (t + 1) * 32;
            const float* bp = Bp + (t + 1) * 32;
#pragma unroll
            for (int i = 0; i < 4; i++) {
                cp_async16(sA + bo + i * 16, ap + i * 4);
                cp_async16(sB + bo + i * 16, bp + i * 4);
            }
            cp_commit();
            cp_wait<1>();
        } else {
            cp_wait<0>();
        }
        __syncthreads();

        const float* Ab = As + (t & 1) * GBUF;
        const float* Bb = Bs + (t & 1) * GBUF;

#pragma unroll
        for (int ks = 0; ks < 4; ks++) {
            uint32_t af[4][4];
#pragma unroll
            for (int mi = 0; mi < 4; mi++) {
                const float* p0 = Ab + (wm + mi * 16 + gid) * GP2 + ks * 8 + tig * 2;
                float2 a01 = *(const float2*)p0;              // k tig / tig+4
                float2 a23 = *(const float2*)(p0 + 8 * GP2);
                af[mi][0] = __float_as_uint(a01.x);
                af[mi][2] = __float_as_uint(a01.y);
                af[mi][1] = __float_as_uint(a23.x);
                af[mi][3] = __float_as_uint(a23.y);
            }
#pragma unroll
            for (int nj = 0; nj < 4; nj++) {
                const float* p = Bb + (wn + nj * 8 + gid) * GP2 + ks * 8 + tig * 2;
                float2 bb = *(const float2*)p;
                const uint32_t b0 = __float_as_uint(bb.x);
                const uint32_t b1 = __float_as_uint(bb.y);
#pragma unroll
                for (int mi = 0; mi < 4; mi++)
                    mma_tf32(acc[mi][nj], af[mi], b0, b1);
            }
        }
        __syncthreads();
    }

#pragma unroll
    for (int nj = 0; nj < 4; nj++) {
        const int col = blockIdx.x * 128 + wn + nj * 8 + tig * 2;
        const float ba0 = bias ? bias[col]     : 0.f;
        const float ba1 = bias ? bias[col + 1] : 0.f;
#pragma unroll
        for (int mi = 0; mi < 4; mi++) {
            const int row = blockIdx.y * 128 + wm + mi * 16 + gid;
            float v00 = acc[mi][nj][0] + ba0;
            float v01 = acc[mi][nj][1] + ba1;
            float v10 = acc[mi][nj][2] + ba0;
            float v11 = acc[mi][nj][3] + ba1;
            if (!doRound) {
                float* cp = C + (size_t)row * Nc + col;
                *(float2*)cp = make_float2(v00, v01);
                *(float2*)(cp + (size_t)8 * Nc) = make_float2(v10, v11);
            } else if (z == 0) {
                float* cp = C + (size_t)row * Nc + col;
                *(float2*)cp = make_float2(tf32rf(v00 * pm), tf32rf(v01 * pm));
                *(float2*)(cp + (size_t)8 * Nc) =
                    make_float2(tf32rf(v10 * pm), tf32rf(v11 * pm));
            } else if (z == 1) {
                // K: pi-permuted rows, d-interleaved cols
                const int rp = (row & ~7) + 2 * (row & 3) + ((row >> 2) & 1);
                const int p0 = (col & ~7) + 2 * (col & 3) + ((col >> 2) & 1);
                const int p1 = (col & ~7) + 2 * ((col + 1) & 3) + (((col + 1) >> 2) & 1);
                float* cp = C + (size_t)rp * Nc;
                cp[p0] = tf32rf(v00);
                cp[p1] = tf32rf(v01);
                cp[(size_t)8 * Nc + p0] = tf32rf(v10);
                cp[(size_t)8 * Nc + p1] = tf32rf(v11);
            } else {
                // V: [frame*8+h][key>>3][d][pi(key&7)]
                const int key = row & (cN - 1);
                const int frame = row >> 10;
                const int hh = col / cD;
                const int dd = col - hh * cD;
                const int pk = 2 * (key & 3) + ((key >> 2) & 1);
                float* p = C + ((size_t)(frame * 8 + hh) * 128 + (key >> 3)) * 640
                             + dd * 8 + pk;
                p[0]   = tf32rf(v00);
                p[8]   = tf32rf(v01);
                p[640] = tf32rf(v10);   // key+8 -> next group
                p[648] = tf32rf(v11);
            }
        }
    }
}

// ---------------------------------------------------------------------------
// Flash attention, mma.sync tf32.  r14 math; ALL staging is now pure copy
// (producers wrote K/V in attention-native layouts):
//   K: 10 LDG.128 -> 10 STS.128 (perm/interleave baked in g_k)
//   V: 10 LDG.128 -> 10 STS.128 contiguous (layout baked in g_v)
// S-loop and PV B-pairs via LDS.64; base-2 softmax (bare ex2); no-max.
// Smem: Qs[128][84] + Ks[128][88] + Vt[16][656] = 130048 B.
// ---------------------------------------------------------------------------
constexpr int QSP = 84;
constexpr int KSP = 88;
constexpr int VGS = 656;                  // 640 data + 16 pad per key-group
constexpr int SM_KS = 128 * QSP;
constexpr int SM_VS = SM_KS + 128 * KSP;
constexpr int ATTN_SMEM = (SM_VS + 16 * VGS) * 4;   // 130048 bytes

__global__ __launch_bounds__(256, 1) void attn_mma(const int* __restrict__ ctx)
{
    extern __shared__ float sm[];
    float* Qs = sm;
    float* Ks = sm + SM_KS;
    float* Vt = sm + SM_VS;

    const int tid  = threadIdx.x;
    const int wid  = tid >> 5;
    const int lane = tid & 31;
    const int gid  = lane >> 2;
    const int tig  = lane & 3;
    const int m0   = wid * 16;

    const int qt = blockIdx.x, h = blockIdx.y, b = blockIdx.z;

    const int r0 = tid >> 1;           // 0..127
    const int d0 = (tid & 1) * 40;     // 0/40
    const int vi  = tid & 15;          // V copy lane-in-group
    const int vgq = tid >> 4;          // V copy group (0..15)

    const int frame0 = ctx[b * cR + 0];
    const int frame1 = ctx[b * cR + 1];
    const int frame2 = ctx[b * cR + 2];

    // ---- stage Q (pre-scaled by SCALE*log2e, pre-rounded: pure copy) ----
    {
        const float* qp = g_q + (size_t)(b * cN + qt * 128 + r0) * cInner + h * cD + d0;
        float* qs = Qs + r0 * QSP + d0;
#pragma unroll
        for (int i = 0; i < 10; i++)
            *(float4*)(qs + i * 4) = *(const float4*)(qp + i * 4);
    }
    __syncthreads();

    // ---- Q A-fragments in registers (reused for all 24 KV tiles) ----
    uint32_t qa[10][4];
#pragma unroll
    for (int k = 0; k < 10; k++) {
        qa[k][0] = __float_as_uint(Qs[(m0 + gid) * QSP + k * 8 + tig]);
        qa[k][1] = __float_as_uint(Qs[(m0 + gid + 8) * QSP + k * 8 + tig]);
        qa[k][2] = __float_as_uint(Qs[(m0 + gid) * QSP + k * 8 + tig + 4]);
        qa[k][3] = __float_as_uint(Qs[(m0 + gid + 8) * QSP + k * 8 + tig + 4]);
    }

    float o[10][4];
#pragma unroll
    for (int n = 0; n < 10; n++)
#pragma unroll
        for (int j = 0; j < 4; j++) o[n][j] = 0.f;
    float llo = 0.f, lhi = 0.f;      // lane-partial row sums

#pragma unroll 1
    for (int t = 0; t < 24; t++) {
        __syncthreads();   // prev tile's readers done before overwrite

        // ---- stage K and V: pure float4 copies (layouts baked by producer) ----
        {
            const int frame = (t >> 3) == 0 ? frame0 : (t >> 3) == 1 ? frame1 : frame2;
            const int kb = (t * 128) & (cN - 1);
            const float* kp = g_k + (size_t)(frame * cN + kb + r0) * cInner + h * cD + d0;
            float* ks = Ks + r0 * KSP + d0;
#pragma unroll
            for (int i = 0; i < 10; i++)
                *(float4*)(ks + i * 4) = *(const float4*)(kp + i * 4);

            const float* vsrc = g_v
                + ((size_t)(frame * 8 + h) * 128 + (kb >> 3) + vgq) * 640 + vi * 4;
            float* vdst = Vt + vgq * VGS + vi * 4;
#pragma unroll
            for (int j = 0; j < 10; j++)
                *(float4*)(vdst + j * 64) = *(const float4*)(vsrc + j * 64);
        }
        __syncthreads();

        // ---- S = Q K^T : 16 n-tiles x 10 k-steps, B-pairs via LDS.64 ----
        float s[16][4];
#pragma unroll
        for (int n = 0; n < 16; n++)
#pragma unroll
            for (int j = 0; j < 4; j++) s[n][j] = 0.f;

#pragma unroll
        for (int n = 0; n < 16; n++) {
            const float* krow = Ks + (n * 8 + gid) * KSP + 2 * tig;
#pragma unroll
            for (int k = 0; k < 10; k++) {
                float2 bb = *(const float2*)(krow + k * 8);
                mma_tf32(s[n], qa[k], __float_as_uint(bb.x), __float_as_uint(bb.y));
            }
        }

        // ---- softmax numerator: base-2 logits -> raw ex2.approx ----
        float rs0 = 0.f, rs1 = 0.f;
#pragma unroll
        for (int n = 0; n < 16; n++) {
            s[n][0] = ex2(s[n][0]); rs0 += s[n][0];
            s[n][1] = ex2(s[n][1]); rs0 += s[n][1];
            s[n][2] = ex2(s[n][2]); rs1 += s[n][2];
            s[n][3] = ex2(s[n][3]); rs1 += s[n][3];
        }
        llo += rs0;
        lhi += rs1;

        // ---- O += P V : C-frag slots ARE the A-frag; B-pairs via LDS.64 ----
#pragma unroll
        for (int kt = 0; kt < 16; kt++) {
            uint32_t pa[4];
            pa[0] = tf32r(s[kt][0]);
            pa[1] = tf32r(s[kt][2]);
            pa[2] = tf32r(s[kt][1]);
            pa[3] = tf32r(s[kt][3]);

            const float* vg = Vt + kt * VGS + gid * 8 + 2 * tig;
#pragma unroll
            for (int n = 0; n < 10; n++) {
                float2 bb = *(const float2*)(vg + n * 64);
                mma_tf32(o[n], pa, __float_as_uint(bb.x), __float_as_uint(bb.y));
            }
        }
    }

    // ---- epilogue: reduce row sums, normalize, write k-INTERLEAVED g_ao ----
    llo += __shfl_xor_sync(0xffffffffu, llo, 1);
    llo += __shfl_xor_sync(0xffffffffu, llo, 2);
    lhi += __shfl_xor_sync(0xffffffffu, lhi, 1);
    lhi += __shfl_xor_sync(0xffffffffu, lhi, 2);
    const float inv0 = 1.f / llo;
    const float inv1 = 1.f / lhi;
    const int c0 = tig * 2, c1 = tig * 2 + 1;
    const int q0 = 2 * (c0 & 3) + ((c0 >> 2) & 1);
    const int q1 = 2 * (c1 & 3) + ((c1 >> 2) & 1);
    float* op0 = g_ao + (size_t)(b * cN + qt * 128 + m0 + gid) * cInner + h * cD;
    float* op1 = op0 + (size_t)8 * cInner;
#pragma unroll
    for (int n = 0; n < 10; n++) {
        op0[n * 8 + q0] = tf32rf(o[n][0] * inv0);
        op0[n * 8 + q1] = tf32rf(o[n][1] * inv0);
        op1[n * 8 + q0] = tf32rf(o[n][2] * inv1);
        op1[n * 8 + q1] = tf32rf(o[n][3] * inv1);
    }
}

// ---------------------------------------------------------------------------
extern "C" void kernel_launch(void* const* d_in, const int* in_sizes, int n_in,
                              void* d_out, int out_size)
{
    const float* x   = (const float*)d_in[0];
    const float* Wq  = (const float*)d_in[1];
    const float* Wk  = (const float*)d_in[2];
    const float* Wv  = (const float*)d_in[3];
    const float* Wo  = (const float*)d_in[4];
    const float* bo  = (const float*)d_in[5];
    const int*   ctx = (const int*)d_in[6];
    float* out = (float*)d_out;

    float* gq;  cudaGetSymbolAddress((void**)&gq, g_q);
    float* gk;  cudaGetSymbolAddress((void**)&gk, g_k);
    float* gv;  cudaGetSymbolAddress((void**)&gv, g_v);
    float* gao; cudaGetSymbolAddress((void**)&gao, g_ao);
    float* gxr; cudaGetSymbolAddress((void**)&gxr, g_xr);
    float* gwq; cudaGetSymbolAddress((void**)&gwq, g_wq);
    float* gwk; cudaGetSymbolAddress((void**)&gwk, g_wk);
    float* gwv; cudaGetSymbolAddress((void**)&gwv, g_wv);
    float* gwo; cudaGetSymbolAddress((void**)&gwo, g_wo);

    static bool attr_set = false;
    if (!attr_set) {
        cudaFuncSetAttribute(attn_mma,
                             cudaFuncAttributeMaxDynamicSharedMemorySize,
                             ATTN_SMEM);
        cudaFuncSetAttribute(gemm_tf32,
                             cudaFuncAttributeMaxDynamicSharedMemorySize,
                             GEMM_SMEM);
        attr_set = true;
    }

    // Pre-round + k-interleave inputs/weights (8 elements per thread).
    pre_round_x<<<(cM * cC) / (256 * 8), 256>>>(x, gxr);
    pre_round_w<<<dim3((cInner * cC) / (256 * 8), 1, 4), 256>>>(
        Wq, Wk, Wv, Wo, gwq, gwk, gwv, gwo);

    // Fused QKV projections; epilogue writes q scaled by SCALE*log2e and
    // k/v in attention-native layouts.
    gemm_tf32<<<dim3(cInner / 128, cM / 128, 3), 256, GEMM_SMEM>>>(
        gxr, gwq, gwk, gwv, gq, gk, gv, nullptr, cM, cInner, cC, SCALE_L2E, 1);

    attn_mma<<<dim3(8, 8, 8), 256, ATTN_SMEM>>>(ctx);

    // Output projection (g_ao and g_wo both k-interleaved; bias fp32).
    gemm_tf32<<<dim3(cC / 128, cM / 128, 1), 256, GEMM_SMEM>>>(
        gao, gwo, gwo, gwo, out, out, out, bo, cM, cC, cInner, 1.0f, 0);
}